// round 4
// baseline (speedup 1.0000x reference)
#include <cuda_runtime.h>
#include <cuda_bf16.h>
#include <mma.h>

using namespace nvcuda;

#define Nn 100000
#define Rr 6
#define Ee 400000
#define Ff 128
#define RE (Rr*Ee)        // 2,400,000 edges total
#define NR (Nn*Rr)        // 600,000 (dst,rel) rows
#define KK (Rr*Ff)        // 768 concat K dim
#define SCAN_BLKS 586     // ceil(NR/1024)

// ---------------- scratch (__device__ globals; no runtime alloc) -------------
__device__ float g_ns[NR];                     // norm_src per (r,n)  (also deg_out count)
__device__ float g_nd[NR];                     // norm_dst per (r,n)  (also deg_in count)
__device__ int   g_counts[NR];                 // CSR row counts, row = dst*6+r
__device__ int   g_off[NR];                    // CSR row offsets (exclusive)
__device__ int   g_cursor[NR];                 // scatter cursors
__device__ int   g_bsum[1024];
__device__ int   g_bscan[1024];
__device__ unsigned g_entries[RE];             // src node per CSR entry
__device__ __nv_bfloat16 g_xb[Nn*Ff];          // bf16 copy of x (25.6 MB, L2-resident)
__device__ __nv_bfloat16 g_agg[(size_t)Nn*KK]; // [N,768] per-relation aggregates (153.6 MB)
__device__ __nv_bfloat16 g_Whi[KK*Ff];         // bf16 W1 concat, high part
__device__ __nv_bfloat16 g_Wlo[KK*Ff];         // bf16 W1 concat, residual (W - hi)
__device__ float g_b1sum[Ff];                  // sum_r b1[r]
__device__ float g_csum[NR];                   // per (r,src): sum over out-edges of norm_dst[dst]
__device__ float g_M[Rr*Ff];                   // M[r] = sum_n w_r[n] * relu(h1[n])

// ---------------- kernels ----------------------------------------------------
__global__ void k_zero() {
    int i = blockIdx.x * blockDim.x + threadIdx.x;
    if (i < NR) { g_ns[i] = 0.f; g_nd[i] = 0.f; g_counts[i] = 0; g_csum[i] = 0.f; }
    if (i < Rr*Ff) g_M[i] = 0.f;
}

__global__ void k_xconv(const float* __restrict__ x) {
    int i = blockIdx.x * blockDim.x + threadIdx.x;
    if (i < Nn*Ff) g_xb[i] = __float2bfloat16(x[i]);
}

__global__ void k_wconv(const float* __restrict__ W1, const float* __restrict__ b1) {
    int i = blockIdx.x * blockDim.x + threadIdx.x;
    if (i < KK*Ff) {
        float w = W1[i];                       // [R,128,128] == [768,128] flat
        __nv_bfloat16 hi = __float2bfloat16(w);
        g_Whi[i] = hi;
        g_Wlo[i] = __float2bfloat16(w - __bfloat162float(hi));
    }
    if (i < Ff) {
        float s = 0.f;
        for (int r = 0; r < Rr; r++) s += b1[r*Ff + i];
        g_b1sum[i] = s;
    }
}

// degrees + CSR row histogram in one pass
__global__ void k_deg(const int* __restrict__ src, const int* __restrict__ dst) {
    int i = blockIdx.x * blockDim.x + threadIdx.x;
    if (i >= RE) return;
    int r = i / Ee;
    int s = src[i], d = dst[i];
    atomicAdd(&g_ns[r*Nn + s], 1.f);
    atomicAdd(&g_nd[r*Nn + d], 1.f);
    atomicAdd(&g_counts[d*Rr + r], 1);
}

__global__ void k_norm() {
    int i = blockIdx.x * blockDim.x + threadIdx.x;
    if (i >= NR) return;
    float a = g_ns[i]; g_ns[i] = (a > 0.f) ? rsqrtf(a) : 0.f;
    float b = g_nd[i]; g_nd[i] = (b > 0.f) ? rsqrtf(b) : 0.f;
}

__global__ void k_scan1() {
    __shared__ int s[1024];
    int b = blockIdx.x, t = threadIdx.x, i = b*1024 + t;
    int v = (i < NR) ? g_counts[i] : 0;
    s[t] = v; __syncthreads();
    for (int off = 1; off < 1024; off <<= 1) {
        int tv = (t >= off) ? s[t-off] : 0;
        __syncthreads(); s[t] += tv; __syncthreads();
    }
    if (i < NR) g_off[i] = s[t] - v;         // exclusive within block
    if (t == 1023) g_bsum[b] = s[1023];
}

__global__ void k_scan2() {
    __shared__ int s[1024];
    int t = threadIdx.x;
    int v = (t < SCAN_BLKS) ? g_bsum[t] : 0;
    s[t] = v; __syncthreads();
    for (int off = 1; off < 1024; off <<= 1) {
        int tv = (t >= off) ? s[t-off] : 0;
        __syncthreads(); s[t] += tv; __syncthreads();
    }
    g_bscan[t] = s[t] - v;                   // exclusive block offsets
}

__global__ void k_scan3() {
    int i = blockIdx.x * blockDim.x + threadIdx.x;
    if (i >= NR) return;
    int o = g_off[i] + g_bscan[i >> 10];
    g_off[i] = o;
    g_cursor[i] = o;
}

__global__ void k_scatter(const int* __restrict__ src, const int* __restrict__ dst) {
    int i = blockIdx.x * blockDim.x + threadIdx.x;
    if (i >= RE) return;
    int r = i / Ee;
    int d = dst[i];
    int pos = atomicAdd(&g_cursor[d*Rr + r], 1);
    g_entries[pos] = (unsigned)src[i];
}

// layer-2 scalar coefficients: csum[r][s] += norm_dst[r][dst] per out-edge
__global__ void k_csum(const int* __restrict__ src, const int* __restrict__ dst) {
    int i = blockIdx.x * blockDim.x + threadIdx.x;
    if (i >= RE) return;
    int r = i / Ee;
    atomicAdd(&g_csum[r*Nn + src[i]], g_nd[r*Nn + dst[i]]);
}

// one warp per (dst, rel) row: AGG[dst][r] = n_dst * sum_e n_src[src] * x[src]
__global__ void k_agg() {
    int wid  = (blockIdx.x * blockDim.x + threadIdx.x) >> 5;
    int lane = threadIdx.x & 31;
    if (wid >= NR) return;
    int dst = wid / Rr, r = wid - dst*Rr;
    int start = g_off[wid], cnt = g_counts[wid];
    float4 acc = make_float4(0.f, 0.f, 0.f, 0.f);
    for (int base = 0; base < cnt; base += 32) {
        int j = base + lane;
        int e = 0; float w = 0.f;
        if (j < cnt) { e = (int)g_entries[start + j]; w = g_ns[r*Nn + e]; }
        int m = min(32, cnt - base);
        for (int k = 0; k < m; k++) {
            int   s  = __shfl_sync(0xffffffffu, e, k);
            float ww = __shfl_sync(0xffffffffu, w, k);
            uint2 u = *(reinterpret_cast<const uint2*>(g_xb + s*Ff) + lane);
            __nv_bfloat162 lo = *reinterpret_cast<__nv_bfloat162*>(&u.x);
            __nv_bfloat162 hi = *reinterpret_cast<__nv_bfloat162*>(&u.y);
            float2 f0 = __bfloat1622float2(lo);
            float2 f1 = __bfloat1622float2(hi);
            acc.x += ww*f0.x; acc.y += ww*f0.y;
            acc.z += ww*f1.x; acc.w += ww*f1.y;
        }
    }
    float nd = g_nd[r*Nn + dst];
    __nv_bfloat162 o0 = __floats2bfloat162_rn(acc.x*nd, acc.y*nd);
    __nv_bfloat162 o1 = __floats2bfloat162_rn(acc.z*nd, acc.w*nd);
    uint2 ou;
    ou.x = *reinterpret_cast<unsigned*>(&o0);
    ou.y = *reinterpret_cast<unsigned*>(&o1);
    *(reinterpret_cast<uint2*>(g_agg + (size_t)dst*KK + r*Ff) + lane) = ou;
}

// h1 = relu(AGG[N,768] @ (Whi+Wlo)[768,128] + b1sum); fused epilogue accumulates
// M[r][col] += w_r[n] * h1[n][col]  with w_r[n] = ns[r][n]*csum[r][n].
// 256 threads, 8 warps (2x4), static smem <= 48KB, no h1 materialization.
__global__ void k_gemm() {
    __shared__ __align__(16) char sm[40960];
    __nv_bfloat16* As = reinterpret_cast<__nv_bfloat16*>(sm);          // 128x32 (8KB)
    __nv_bfloat16* Bh = reinterpret_cast<__nv_bfloat16*>(sm + 8192);   // 32x128 (8KB)
    __nv_bfloat16* Bl = reinterpret_cast<__nv_bfloat16*>(sm + 16384);  // 32x128 (8KB)
    int t = threadIdx.x, warp = t >> 5;
    int wm = warp >> 2, wn = warp & 3;          // 2 x 4 warp grid, each 64x32
    wmma::fragment<wmma::accumulator, 16, 16, 16, float> acc[4][2];
    #pragma unroll
    for (int i = 0; i < 4; i++)
        #pragma unroll
        for (int j = 0; j < 2; j++) wmma::fill_fragment(acc[i][j], 0.f);

    int rowbase = blockIdx.x * 128;
    for (int kk = 0; kk < KK; kk += 32) {
        #pragma unroll
        for (int u = t; u < 512; u += 256) {              // A: 128x32 bf16
            int row = u >> 2, c = (u & 3) * 8;
            int gr = rowbase + row;
            uint4 v = make_uint4(0u, 0u, 0u, 0u);
            if (gr < Nn)
                v = *reinterpret_cast<const uint4*>(g_agg + (size_t)gr*KK + kk + c);
            *reinterpret_cast<uint4*>(As + row*32 + c) = v;
        }
        #pragma unroll
        for (int u = t; u < 512; u += 256) {              // B hi+lo: 32x128 bf16 each
            int row = u >> 4, c = (u & 15) * 8;
            *reinterpret_cast<uint4*>(Bh + row*128 + c) =
                *reinterpret_cast<const uint4*>(g_Whi + (kk + row)*128 + c);
            *reinterpret_cast<uint4*>(Bl + row*128 + c) =
                *reinterpret_cast<const uint4*>(g_Wlo + (kk + row)*128 + c);
        }
        __syncthreads();
        #pragma unroll
        for (int kf = 0; kf < 32; kf += 16) {
            wmma::fragment<wmma::matrix_a, 16, 16, 16, __nv_bfloat16, wmma::row_major> af[4];
            wmma::fragment<wmma::matrix_b, 16, 16, 16, __nv_bfloat16, wmma::row_major> bh[2], bl[2];
            #pragma unroll
            for (int i = 0; i < 4; i++)
                wmma::load_matrix_sync(af[i], As + (wm*64 + i*16)*32 + kf, 32);
            #pragma unroll
            for (int j = 0; j < 2; j++) {
                wmma::load_matrix_sync(bh[j], Bh + kf*128 + wn*32 + j*16, 128);
                wmma::load_matrix_sync(bl[j], Bl + kf*128 + wn*32 + j*16, 128);
            }
            #pragma unroll
            for (int i = 0; i < 4; i++)
                #pragma unroll
                for (int j = 0; j < 2; j++) {
                    wmma::mma_sync(acc[i][j], af[i], bh[j], acc[i][j]);
                    wmma::mma_sync(acc[i][j], af[i], bl[j], acc[i][j]);
                }
        }
        __syncthreads();
    }

    // ---- fused epilogue: relu + weighted reduction into g_M ----
    float* Cs = reinterpret_cast<float*>(sm);                // 64x128 f32 (32KB)
    float* wc = reinterpret_cast<float*>(sm + 32768);        // [6][64]   (1.5KB)
    float* Mp = reinterpret_cast<float*>(sm + 32768 + 1536); // [2][6][128] (6KB)

    int col  = t & 127;
    int half = t >> 7;                     // 0: rows 0-31 of pass, 1: rows 32-63
    float b1s = g_b1sum[col];
    float ma[Rr];
    #pragma unroll
    for (int r = 0; r < Rr; r++) ma[r] = 0.f;

    #pragma unroll
    for (int p = 0; p < 2; p++) {
        // warps with wm==p store their 64x128 C half
        if (wm == p) {
            #pragma unroll
            for (int i = 0; i < 4; i++)
                #pragma unroll
                for (int j = 0; j < 2; j++)
                    wmma::store_matrix_sync(Cs + (i*16)*128 + wn*32 + j*16,
                                            acc[i][j], 128, wmma::mem_row_major);
        }
        // wcoef for this pass's 64 global rows (384 entries, strided over 256 threads)
        for (int u = t; u < Rr*64; u += 256) {
            int r = u >> 6, row = u & 63;
            int gr = rowbase + p*64 + row;
            wc[r*64 + row] = (gr < Nn) ? g_ns[r*Nn + gr] * g_csum[r*Nn + gr] : 0.f;
        }
        __syncthreads();
        #pragma unroll 4
        for (int rw = 0; rw < 32; rw++) {
            int row = half*32 + rw;
            float v = fmaxf(Cs[row*128 + col] + b1s, 0.f);   // h1 element (fp32)
            #pragma unroll
            for (int r = 0; r < Rr; r++)
                ma[r] += wc[r*64 + row] * v;                  // wc==0 for OOB rows
        }
        __syncthreads();
    }
    #pragma unroll
    for (int r = 0; r < Rr; r++) Mp[(half*Rr + r)*128 + col] = ma[r];
    __syncthreads();
    for (int u = t; u < Rr*Ff; u += 256)                      // 768 entries, strided
        atomicAdd(&g_M[u], Mp[u] + Mp[Rr*Ff + u]);
}

// g = (1/N) sum_r M[r] @ W2_r + sum_r b2_r ; out = g @ Wc + bc
__global__ void k_out(const float* __restrict__ W2, const float* __restrict__ b2,
                      const float* __restrict__ Wc, const float* __restrict__ bc,
                      float* __restrict__ out) {
    __shared__ float g[Ff];
    int t = threadIdx.x;
    float acc = 0.f, bb = 0.f;
    for (int r = 0; r < Rr; r++) {
        const float* W2r = W2 + r*Ff*Ff;
        for (int h = 0; h < Ff; h++)
            acc += g_M[r*Ff + h] * W2r[h*Ff + t];
        bb += b2[r*Ff + t];
    }
    g[t] = acc * (1.f / (float)Nn) + bb;
    __syncthreads();
    if (t < 2) {
        float o = bc[t];
        for (int h = 0; h < Ff; h++) o += g[h] * Wc[h*2 + t];
        out[t] = o;
    }
}

// ---------------- launch ------------------------------------------------------
extern "C" void kernel_launch(void* const* d_in, const int* in_sizes, int n_in,
                              void* d_out, int out_size) {
    const float* x    = (const float*)d_in[0];
    const int*   esrc = (const int*)  d_in[1];
    const int*   edst = (const int*)  d_in[2];
    const float* W1   = (const float*)d_in[3];
    const float* b1   = (const float*)d_in[4];
    const float* W2   = (const float*)d_in[5];
    const float* b2   = (const float*)d_in[6];
    const float* Wc   = (const float*)d_in[7];
    const float* bc   = (const float*)d_in[8];
    float* out = (float*)d_out;

    k_zero   <<<(NR + 255)/256, 256>>>();
    k_xconv  <<<(Nn*Ff + 255)/256, 256>>>(x);
    k_wconv  <<<(KK*Ff + 255)/256, 256>>>(W1, b1);
    k_deg    <<<(RE + 255)/256, 256>>>(esrc, edst);
    k_norm   <<<(NR + 255)/256, 256>>>();
    k_scan1  <<<SCAN_BLKS, 1024>>>();
    k_scan2  <<<1, 1024>>>();
    k_scan3  <<<SCAN_BLKS, 1024>>>();
    k_scatter<<<(RE + 255)/256, 256>>>(esrc, edst);
    k_csum   <<<(RE + 255)/256, 256>>>(esrc, edst);
    k_agg    <<<NR/8, 256>>>();                       // 600000 rows, 8 warps/block
    k_gemm   <<<(Nn + 127)/128, 256>>>();
    k_out    <<<1, 128>>>(W2, b2, Wc, bc, out);
}